// round 2
// baseline (speedup 1.0000x reference)
#include <cuda_runtime.h>
#include <cuda_bf16.h>

#define N_NODES 100000
#define N_EDGES 1600000
#define IN_F    128
#define HD      64      // H*D
#define H       4
#define D       16
#define FE      32
#define NT      8

// ---------------- scratch (no allocs allowed) ----------------
__device__ float g_feat[N_NODES * HD];     // 25.6 MB
__device__ float g_el[N_NODES * H];
__device__ float g_er[N_NODES * H];
__device__ float g_w[N_EDGES * H];         // 25.6 MB  exp(leakyrelu(logit))
__device__ float g_denom[N_NODES * H];
__device__ float g_ee[NT * H];

// vector reductions via PTX (sm_90+)
__device__ __forceinline__ void red_add_v4(float* p, float a, float b, float c, float d) {
    asm volatile("red.global.add.v4.f32 [%0], {%1,%2,%3,%4};"
                 :: "l"(p), "f"(a), "f"(b), "f"(c), "f"(d) : "memory");
}
__device__ __forceinline__ void red_add_v2(float* p, float a, float b) {
    asm volatile("red.global.add.v2.f32 [%0], {%1,%2};"
                 :: "l"(p), "f"(a), "f"(b) : "memory");
}

// ---------------- K0: zero out + denom ----------------
__global__ void k_zero(float* __restrict__ out) {
    int tid = blockIdx.x * blockDim.x + threadIdx.x;
    int stride = gridDim.x * blockDim.x;
    float4 z = make_float4(0.f, 0.f, 0.f, 0.f);
    int tot4 = (N_NODES * HD) / 4;
    for (int i = tid; i < tot4; i += stride) ((float4*)out)[i] = z;
    int dn4 = (N_NODES * H) / 4;
    for (int i = tid; i < dn4; i += stride) ((float4*)g_denom)[i] = z;
}

// ---------------- Kee: 8x4 edge-type attention table ----------------
__global__ void k_ee(const float* __restrict__ edge_emb,
                     const float* __restrict__ fc_e_w,
                     const float* __restrict__ attn_e) {
    int t = threadIdx.x >> 2;   // 0..7
    int h = threadIdx.x & 3;    // 0..3
    if (threadIdx.x < 32) {
        float s = 0.f;
        for (int f = 0; f < FE; f++) {
            float ef = 0.f;
            const float* wr = fc_e_w + (h * FE + f) * FE;
            const float* em = edge_emb + t * FE;
            for (int c = 0; c < FE; c++) ef += em[c] * wr[c];
            s += ef * attn_e[h * FE + f];
        }
        g_ee[t * H + h] = s;
    }
}

// ---------------- K1: feat = x @ fc_w^T  (+ fused el/er) ----------------
// block 256 = 16 colgroups x 16 rowgroups; 64 nodes / block-iter;
// thread micro-tile: 4 nodes x 4 cols.
#define SXPITCH 132
#define SMEM_K1_FLOATS (IN_F * HD + 64 * SXPITCH + 128)
__global__ void __launch_bounds__(256, 3)
k_feat(const float* __restrict__ x, const float* __restrict__ fc_w,
       const float* __restrict__ attn_l, const float* __restrict__ attn_r) {
    extern __shared__ float smem[];
    float* sW  = smem;                       // [128][64]  sW[k*64+j]
    float* sX  = sW + IN_F * HD;             // [64][132]
    float* sAl = sX + 64 * SXPITCH;          // [64]
    float* sAr = sAl + 64;                   // [64]

    int tx = threadIdx.x;
    for (int i = tx; i < IN_F * HD; i += 256) {
        int j = i >> 7, k = i & 127;         // fc_w[j][k]
        sW[k * HD + j] = fc_w[i];
    }
    if (tx < HD) { sAl[tx] = attn_l[tx]; sAr[tx] = attn_r[tx]; }

    int tc = tx & 15;    // cols 4tc..4tc+3
    int tr = tx >> 4;    // 0..15
    int h  = tc >> 2;

    for (int n0 = blockIdx.x * 64; n0 < N_NODES; n0 += gridDim.x * 64) {
        __syncthreads();
        // load 64-node x tile (float4 coalesced)
        const float4* xg = (const float4*)x;
        for (int v = tx; v < 64 * 32; v += 256) {
            int node = v >> 5, kq = v & 31;
            int gn = n0 + node;
            float4 val = (gn < N_NODES) ? xg[gn * 32 + kq]
                                        : make_float4(0.f, 0.f, 0.f, 0.f);
            *(float4*)&sX[node * SXPITCH + kq * 4] = val;
        }
        __syncthreads();

        const float* px0 = sX + tr * SXPITCH;
        const float* px1 = px0 + 16 * SXPITCH;
        const float* px2 = px1 + 16 * SXPITCH;
        const float* px3 = px2 + 16 * SXPITCH;

        float a00=0,a01=0,a02=0,a03=0, a10=0,a11=0,a12=0,a13=0;
        float a20=0,a21=0,a22=0,a23=0, a30=0,a31=0,a32=0,a33=0;
        #pragma unroll 4
        for (int k = 0; k < IN_F; k++) {
            float4 w4 = *(const float4*)(sW + k * HD + tc * 4);
            float x0 = px0[k], x1 = px1[k], x2 = px2[k], x3 = px3[k];
            a00 += x0*w4.x; a01 += x0*w4.y; a02 += x0*w4.z; a03 += x0*w4.w;
            a10 += x1*w4.x; a11 += x1*w4.y; a12 += x1*w4.z; a13 += x1*w4.w;
            a20 += x2*w4.x; a21 += x2*w4.y; a22 += x2*w4.z; a23 += x2*w4.w;
            a30 += x3*w4.x; a31 += x3*w4.y; a32 += x3*w4.z; a33 += x3*w4.w;
        }

        float l0 = sAl[tc*4], l1 = sAl[tc*4+1], l2 = sAl[tc*4+2], l3 = sAl[tc*4+3];
        float r0 = sAr[tc*4], r1 = sAr[tc*4+1], r2 = sAr[tc*4+2], r3 = sAr[tc*4+3];

        #pragma unroll
        for (int i = 0; i < 4; i++) {
            float c0,c1,c2,c3;
            if (i==0){c0=a00;c1=a01;c2=a02;c3=a03;}
            else if (i==1){c0=a10;c1=a11;c2=a12;c3=a13;}
            else if (i==2){c0=a20;c1=a21;c2=a22;c3=a23;}
            else {c0=a30;c1=a31;c2=a32;c3=a33;}
            float pl = c0*l0 + c1*l1 + c2*l2 + c3*l3;
            float pr = c0*r0 + c1*r1 + c2*r2 + c3*r3;
            // reduce across the 4 colgroups of one head (lanes tc, tc^1, tc^2)
            pl += __shfl_xor_sync(0xffffffffu, pl, 1, 4);
            pl += __shfl_xor_sync(0xffffffffu, pl, 2, 4);
            pr += __shfl_xor_sync(0xffffffffu, pr, 1, 4);
            pr += __shfl_xor_sync(0xffffffffu, pr, 2, 4);
            int n = n0 + tr + i * 16;
            if (n < N_NODES) {
                *(float4*)&g_feat[n * HD + tc * 4] = make_float4(c0, c1, c2, c3);
                if ((tc & 3) == 0) {
                    g_el[n * H + h] = pl;
                    g_er[n * H + h] = pr;
                }
            }
        }
    }
}

// ---------------- K2: per-edge exp weights + denom scatter ----------------
// 2 edges per thread (grid-stride) for higher MLP on the index gathers.
__global__ void __launch_bounds__(256)
k_edge1(const int* __restrict__ src, const int* __restrict__ dst,
        const int* __restrict__ etype) {
    int tid = blockIdx.x * blockDim.x + threadIdx.x;
    int stride = gridDim.x * blockDim.x;
    for (int i = tid; i < N_EDGES; i += stride) {
        int s = __ldg(&src[i]), d = __ldg(&dst[i]), t = __ldg(&etype[i]);
        float4 l = *(const float4*)&g_el[s * 4];
        float4 r = *(const float4*)&g_er[d * 4];
        const float* ee = &g_ee[t * 4];
        float e0 = l.x + r.x + ee[0];
        float e1 = l.y + r.y + ee[1];
        float e2 = l.z + r.z + ee[2];
        float e3 = l.w + r.w + ee[3];
        e0 = e0 > 0.f ? e0 : 0.2f * e0;
        e1 = e1 > 0.f ? e1 : 0.2f * e1;
        e2 = e2 > 0.f ? e2 : 0.2f * e2;
        e3 = e3 > 0.f ? e3 : 0.2f * e3;
        float4 w = make_float4(__expf(e0), __expf(e1), __expf(e2), __expf(e3));
        *(float4*)&g_w[i * 4] = w;
        red_add_v4(&g_denom[d * 4], w.x, w.y, w.z, w.w);
    }
}

// ---------------- K3: warp-per-edge weighted message scatter ----------------
__global__ void __launch_bounds__(256)
k_edge2(const int* __restrict__ src, const int* __restrict__ dst,
        float* __restrict__ out) {
    int gtid  = blockIdx.x * blockDim.x + threadIdx.x;
    int warp  = gtid >> 5;
    int lane  = threadIdx.x & 31;
    int nwarp = (gridDim.x * blockDim.x) >> 5;
    int col   = lane * 2;
    int h     = lane >> 3;
    for (int i = warp; i < N_EDGES; i += nwarp) {
        int s = __ldg(&src[i]), d = __ldg(&dst[i]);
        float4 w  = *(const float4*)&g_w[i * 4];
        float4 dn = *(const float4*)&g_denom[d * 4];
        float wh = (h == 0) ? w.x  : (h == 1) ? w.y  : (h == 2) ? w.z  : w.w;
        float dh = (h == 0) ? dn.x : (h == 1) ? dn.y : (h == 2) ? dn.z : dn.w;
        float a = __fdividef(wh, dh);
        float2 f = *(const float2*)&g_feat[s * HD + col];
        red_add_v2(&out[d * HD + col], f.x * a, f.y * a);
    }
}

// ---------------- launch ----------------
extern "C" void kernel_launch(void* const* d_in, const int* in_sizes, int n_in,
                              void* d_out, int out_size) {
    const float* x        = (const float*)d_in[0];
    const int*   src      = (const int*)  d_in[1];
    const int*   dst      = (const int*)  d_in[2];
    const int*   etype    = (const int*)  d_in[3];
    const float* fc_w     = (const float*)d_in[4];
    const float* fc_e_w   = (const float*)d_in[5];
    const float* edge_emb = (const float*)d_in[6];
    const float* attn_l   = (const float*)d_in[7];
    const float* attn_r   = (const float*)d_in[8];
    const float* attn_e   = (const float*)d_in[9];
    float* out = (float*)d_out;

    k_zero<<<1024, 256>>>(out);
    k_ee<<<1, 32>>>(edge_emb, fc_e_w, attn_e);

    size_t smem = SMEM_K1_FLOATS * sizeof(float);   // ~67 KB
    cudaFuncSetAttribute(k_feat, cudaFuncAttributeMaxDynamicSharedMemorySize, (int)smem);
    k_feat<<<444, 256, smem>>>(x, fc_w, attn_l, attn_r);

    k_edge1<<<3200, 256>>>(src, dst, etype);
    k_edge2<<<4736, 256>>>(src, dst, out);
}

// round 4
// speedup vs baseline: 1.0947x; 1.0947x over previous
#include <cuda_runtime.h>
#include <cuda_bf16.h>

#define N_NODES 100000
#define N_EDGES 1600000
#define IN_F    128
#define HD      64      // H*D
#define H       4
#define D       16
#define FE      32
#define NT      8
#define NBLK    98      // ceil(N_NODES/1024)

// ---------------- scratch (no allocs allowed) ----------------
__device__ float g_feat[N_NODES * HD];       // 25.6 MB
__device__ float g_el[N_NODES * H];
__device__ float g_er[N_NODES * H];
__device__ float g_w[N_EDGES * H];           // 25.6 MB  exp(leakyrelu(logit))
__device__ float g_ee[NT * H];
__device__ int   g_cnt[N_NODES];             // in-degree histogram
__device__ int   g_rs[N_NODES];              // row start (exclusive scan)
__device__ int   g_fill[N_NODES];            // scatter cursors
__device__ int   g_bsum[NBLK];               // scan block sums
__device__ float g_edata[N_EDGES * 8];       // 51.2 MB: per slot {w0..w3, src, pad}

// ---------------- K0: zero histogram ----------------
__global__ void k_init() {
    int i = blockIdx.x * blockDim.x + threadIdx.x;
    if (i < N_NODES) g_cnt[i] = 0;
}

// ---------------- Kee: 8x4 edge-type attention table ----------------
__global__ void k_ee(const float* __restrict__ edge_emb,
                     const float* __restrict__ fc_e_w,
                     const float* __restrict__ attn_e) {
    int t = threadIdx.x >> 2;   // 0..7
    int h = threadIdx.x & 3;    // 0..3
    if (threadIdx.x < 32) {
        float s = 0.f;
        for (int f = 0; f < FE; f++) {
            float ef = 0.f;
            const float* wr = fc_e_w + (h * FE + f) * FE;
            const float* em = edge_emb + t * FE;
            for (int c = 0; c < FE; c++) ef += em[c] * wr[c];
            s += ef * attn_e[h * FE + f];
        }
        g_ee[t * H + h] = s;
    }
}

// ---------------- K1: feat = x @ fc_w^T  (+ fused el/er) ----------------
#define SXPITCH 132
#define SMEM_K1_FLOATS (IN_F * HD + 64 * SXPITCH + 128)
__global__ void __launch_bounds__(256, 3)
k_feat(const float* __restrict__ x, const float* __restrict__ fc_w,
       const float* __restrict__ attn_l, const float* __restrict__ attn_r) {
    extern __shared__ float smem[];
    float* sW  = smem;                       // [128][64]  sW[k*64+j]
    float* sX  = sW + IN_F * HD;             // [64][132]
    float* sAl = sX + 64 * SXPITCH;          // [64]
    float* sAr = sAl + 64;                   // [64]

    int tx = threadIdx.x;
    for (int i = tx; i < IN_F * HD; i += 256) {
        int j = i >> 7, k = i & 127;         // fc_w[j][k]
        sW[k * HD + j] = fc_w[i];
    }
    if (tx < HD) { sAl[tx] = attn_l[tx]; sAr[tx] = attn_r[tx]; }

    int tc = tx & 15;    // cols 4tc..4tc+3
    int tr = tx >> 4;    // 0..15
    int h  = tc >> 2;

    for (int n0 = blockIdx.x * 64; n0 < N_NODES; n0 += gridDim.x * 64) {
        __syncthreads();
        const float4* xg = (const float4*)x;
        for (int v = tx; v < 64 * 32; v += 256) {
            int node = v >> 5, kq = v & 31;
            int gn = n0 + node;
            float4 val = (gn < N_NODES) ? xg[gn * 32 + kq]
                                        : make_float4(0.f, 0.f, 0.f, 0.f);
            *(float4*)&sX[node * SXPITCH + kq * 4] = val;
        }
        __syncthreads();

        const float* px0 = sX + tr * SXPITCH;
        const float* px1 = px0 + 16 * SXPITCH;
        const float* px2 = px1 + 16 * SXPITCH;
        const float* px3 = px2 + 16 * SXPITCH;

        float a00=0,a01=0,a02=0,a03=0, a10=0,a11=0,a12=0,a13=0;
        float a20=0,a21=0,a22=0,a23=0, a30=0,a31=0,a32=0,a33=0;
        #pragma unroll 4
        for (int k = 0; k < IN_F; k++) {
            float4 w4 = *(const float4*)(sW + k * HD + tc * 4);
            float x0 = px0[k], x1 = px1[k], x2 = px2[k], x3 = px3[k];
            a00 += x0*w4.x; a01 += x0*w4.y; a02 += x0*w4.z; a03 += x0*w4.w;
            a10 += x1*w4.x; a11 += x1*w4.y; a12 += x1*w4.z; a13 += x1*w4.w;
            a20 += x2*w4.x; a21 += x2*w4.y; a22 += x2*w4.z; a23 += x2*w4.w;
            a30 += x3*w4.x; a31 += x3*w4.y; a32 += x3*w4.z; a33 += x3*w4.w;
        }

        float l0 = sAl[tc*4], l1 = sAl[tc*4+1], l2 = sAl[tc*4+2], l3 = sAl[tc*4+3];
        float r0 = sAr[tc*4], r1 = sAr[tc*4+1], r2 = sAr[tc*4+2], r3 = sAr[tc*4+3];

        #pragma unroll
        for (int i = 0; i < 4; i++) {
            float c0,c1,c2,c3;
            if (i==0){c0=a00;c1=a01;c2=a02;c3=a03;}
            else if (i==1){c0=a10;c1=a11;c2=a12;c3=a13;}
            else if (i==2){c0=a20;c1=a21;c2=a22;c3=a23;}
            else {c0=a30;c1=a31;c2=a32;c3=a33;}
            float pl = c0*l0 + c1*l1 + c2*l2 + c3*l3;
            float pr = c0*r0 + c1*r1 + c2*r2 + c3*r3;
            pl += __shfl_xor_sync(0xffffffffu, pl, 1, 4);
            pl += __shfl_xor_sync(0xffffffffu, pl, 2, 4);
            pr += __shfl_xor_sync(0xffffffffu, pr, 1, 4);
            pr += __shfl_xor_sync(0xffffffffu, pr, 2, 4);
            int n = n0 + tr + i * 16;
            if (n < N_NODES) {
                *(float4*)&g_feat[n * HD + tc * 4] = make_float4(c0, c1, c2, c3);
                if ((tc & 3) == 0) {
                    g_el[n * H + h] = pl;
                    g_er[n * H + h] = pr;
                }
            }
        }
    }
}

// ---------------- K2: per-edge exp weights + dst histogram ----------------
__global__ void __launch_bounds__(256)
k_edge1(const int* __restrict__ src, const int* __restrict__ dst,
        const int* __restrict__ etype) {
    int tid = blockIdx.x * blockDim.x + threadIdx.x;
    int stride = gridDim.x * blockDim.x;
    for (int i = tid; i < N_EDGES; i += stride) {
        int s = __ldg(&src[i]), d = __ldg(&dst[i]), t = __ldg(&etype[i]);
        float4 l = *(const float4*)&g_el[s * 4];
        float4 r = *(const float4*)&g_er[d * 4];
        const float* ee = &g_ee[t * 4];
        float e0 = l.x + r.x + ee[0];
        float e1 = l.y + r.y + ee[1];
        float e2 = l.z + r.z + ee[2];
        float e3 = l.w + r.w + ee[3];
        e0 = e0 > 0.f ? e0 : 0.2f * e0;
        e1 = e1 > 0.f ? e1 : 0.2f * e1;
        e2 = e2 > 0.f ? e2 : 0.2f * e2;
        e3 = e3 > 0.f ? e3 : 0.2f * e3;
        float4 w = make_float4(__expf(e0), __expf(e1), __expf(e2), __expf(e3));
        *(float4*)&g_w[i * 4] = w;
        atomicAdd(&g_cnt[d], 1);
    }
}

// ---------------- scan (3 kernels) ----------------
__global__ void __launch_bounds__(1024) k_scan1() {
    int tid = threadIdx.x;
    int gi = blockIdx.x * 1024 + tid;
    int v = (gi < N_NODES) ? g_cnt[gi] : 0;
    int x = v;
    #pragma unroll
    for (int o = 1; o < 32; o <<= 1) {
        int y = __shfl_up_sync(0xffffffffu, x, o);
        if ((tid & 31) >= o) x += y;
    }
    __shared__ int wsum[32];
    if ((tid & 31) == 31) wsum[tid >> 5] = x;
    __syncthreads();
    if (tid < 32) {
        int y = wsum[tid];
        #pragma unroll
        for (int o = 1; o < 32; o <<= 1) {
            int z = __shfl_up_sync(0xffffffffu, y, o);
            if (tid >= o) y += z;
        }
        wsum[tid] = y;
    }
    __syncthreads();
    int base = (tid >= 32) ? wsum[(tid >> 5) - 1] : 0;
    int incl = x + base;
    if (gi < N_NODES) g_rs[gi] = incl - v;       // block-local exclusive
    if (tid == 1023) g_bsum[blockIdx.x] = incl;  // block total
}

__global__ void k_scan2() {   // 1 block, 128 threads, scans NBLK totals
    __shared__ int sh[128];
    int t = threadIdx.x;
    int v = (t < NBLK) ? g_bsum[t] : 0;
    sh[t] = v;
    __syncthreads();
    #pragma unroll
    for (int o = 1; o < 128; o <<= 1) {
        int y = (t >= o) ? sh[t - o] : 0;
        __syncthreads();
        sh[t] += y;
        __syncthreads();
    }
    if (t < NBLK) g_bsum[t] = sh[t] - v;         // exclusive
}

__global__ void __launch_bounds__(1024) k_scan3() {
    int gi = blockIdx.x * 1024 + threadIdx.x;
    if (gi < N_NODES) {
        int r = g_rs[gi] + g_bsum[blockIdx.x];
        g_rs[gi] = r;
        g_fill[gi] = r;
    }
}

// ---------------- K-scatter: build dst-grouped edge records ----------------
__global__ void __launch_bounds__(256)
k_scatter(const int* __restrict__ src, const int* __restrict__ dst) {
    int i = blockIdx.x * blockDim.x + threadIdx.x;
    if (i >= N_EDGES) return;
    int d = __ldg(&dst[i]);
    int pos = atomicAdd(&g_fill[d], 1);
    float4 w = *(const float4*)&g_w[i * 4];
    float* ed = &g_edata[(size_t)pos * 8];
    *(float4*)ed = w;
    ed[4] = __int_as_float(__ldg(&src[i]));
}

// ---------------- K-gather: warp per dst node, software-pipelined ----------------
__global__ void __launch_bounds__(256)
k_gather(float* __restrict__ out) {
    int node = (blockIdx.x * blockDim.x + threadIdx.x) >> 5;
    if (node >= N_NODES) return;
    int lane = threadIdx.x & 31;
    int col  = lane * 2;
    int h    = lane >> 3;
    int start = g_rs[node];
    int cnt   = g_cnt[node];
    float accx = 0.f, accy = 0.f, accw = 0.f;

    if (cnt > 0) {
        // prologue: load record 0
        const float* ed = &g_edata[(size_t)start * 8];
        float4 w = *(const float4*)ed;
        int   s = __float_as_int(ed[4]);
        for (int e = start + 1; e < start + cnt; e++) {
            // issue next record + this feat before consuming (MLP=3)
            const float* edn = &g_edata[(size_t)e * 8];
            float4 wn = *(const float4*)edn;
            int   sn  = __float_as_int(edn[4]);
            float2 f  = *(const float2*)&g_feat[s * HD + col];
            float wh = (h == 0) ? w.x : (h == 1) ? w.y : (h == 2) ? w.z : w.w;
            accw += wh;
            accx += f.x * wh;
            accy += f.y * wh;
            w = wn; s = sn;
        }
        float2 f = *(const float2*)&g_feat[s * HD + col];
        float wh = (h == 0) ? w.x : (h == 1) ? w.y : (h == 2) ? w.z : w.w;
        accw += wh;
        accx += f.x * wh;
        accy += f.y * wh;
    }
    float inv = (cnt > 0) ? __fdividef(1.f, accw) : 0.f;
    float2 r = make_float2(accx * inv, accy * inv);
    *(float2*)&out[node * HD + col] = r;
}

// ---------------- launch ----------------
extern "C" void kernel_launch(void* const* d_in, const int* in_sizes, int n_in,
                              void* d_out, int out_size) {
    const float* x        = (const float*)d_in[0];
    const int*   src      = (const int*)  d_in[1];
    const int*   dst      = (const int*)  d_in[2];
    const int*   etype    = (const int*)  d_in[3];
    const float* fc_w     = (const float*)d_in[4];
    const float* fc_e_w   = (const float*)d_in[5];
    const float* edge_emb = (const float*)d_in[6];
    const float* attn_l   = (const float*)d_in[7];
    const float* attn_r   = (const float*)d_in[8];
    const float* attn_e   = (const float*)d_in[9];
    float* out = (float*)d_out;

    k_init<<<(N_NODES + 255) / 256, 256>>>();
    k_ee<<<1, 32>>>(edge_emb, fc_e_w, attn_e);

    size_t smem = SMEM_K1_FLOATS * sizeof(float);   // ~67 KB
    cudaFuncSetAttribute(k_feat, cudaFuncAttributeMaxDynamicSharedMemorySize, (int)smem);
    k_feat<<<444, 256, smem>>>(x, fc_w, attn_l, attn_r);

    k_edge1<<<3200, 256>>>(src, dst, etype);

    k_scan1<<<NBLK, 1024>>>();
    k_scan2<<<1, 128>>>();
    k_scan3<<<NBLK, 1024>>>();

    k_scatter<<<(N_EDGES + 255) / 256, 256>>>(src, dst);
    k_gather<<<(N_NODES * 32 + 255) / 256, 256>>>(out);
}